// round 7
// baseline (speedup 1.0000x reference)
#include <cuda_runtime.h>
#include <cuda_bf16.h>
#include <math.h>
#include <stdint.h>

#define B_  4
#define L_  2048
#define D_  2048
#define H_  16
#define HD_ 128
#define M_  (B_ * L_)   // 8192
#define E3_ (3 * D_)    // 6144

// ---------------- scratch (allocation-free rule) ----------------
__device__ float g_qkv[(size_t)M_ * E3_];
__device__ __nv_bfloat16 g_xh[(size_t)M_ * D_], g_xl[(size_t)M_ * D_];
__device__ __nv_bfloat16 g_wqh[(size_t)E3_ * D_], g_wql[(size_t)E3_ * D_];
__device__ __nv_bfloat16 g_woh[(size_t)D_ * D_], g_wol[(size_t)D_ * D_];
__device__ __nv_bfloat16 g_yh[(size_t)M_ * D_], g_yl[(size_t)M_ * D_];
__device__ __nv_bfloat16 g_qh[(size_t)M_ * D_], g_ql[(size_t)M_ * D_];
__device__ __nv_bfloat16 g_kh[(size_t)M_ * D_], g_kl[(size_t)M_ * D_];
__device__ __nv_bfloat16 g_vth[(size_t)M_ * D_], g_vtl[(size_t)M_ * D_];
__device__ float g_cos[L_ * 64], g_sin[L_ * 64];

// ---------------- helpers ----------------
__device__ __forceinline__ uint32_t smem_u32(const void* p) {
    uint32_t a;
    asm("{ .reg .u64 t; cvta.to.shared.u64 t, %1; cvt.u32.u64 %0, t; }" : "=r"(a) : "l"(p));
    return a;
}
#define CP16(dst, src)  asm volatile("cp.async.cg.shared.global [%0], [%1], 16;" :: "r"(dst), "l"(src) : "memory")
#define CP_COMMIT()     asm volatile("cp.async.commit_group;" ::: "memory")
#define CP_WAIT0()      asm volatile("cp.async.wait_group 0;" ::: "memory")
#define CP_WAIT1()      asm volatile("cp.async.wait_group 1;" ::: "memory")
#define SWZ(o) ((o) ^ (((o) >> 3) & 0x70))

#define LDSM4(r0, r1, r2, r3, addr) \
    asm volatile("ldmatrix.sync.aligned.m8n8.x4.shared.b16 {%0,%1,%2,%3}, [%4];" \
        : "=r"(r0), "=r"(r1), "=r"(r2), "=r"(r3) : "r"(addr))

__device__ __forceinline__ void mma_bf16(float* c, const uint32_t* a, uint32_t b0, uint32_t b1) {
    asm volatile(
        "mma.sync.aligned.m16n8k16.row.col.f32.bf16.bf16.f32 "
        "{%0,%1,%2,%3}, {%4,%5,%6,%7}, {%8,%9}, {%0,%1,%2,%3};"
        : "+f"(c[0]), "+f"(c[1]), "+f"(c[2]), "+f"(c[3])
        : "r"(a[0]), "r"(a[1]), "r"(a[2]), "r"(a[3]), "r"(b0), "r"(b1));
}

__device__ __forceinline__ uint32_t pack_bf16(float a, float b) {
    __nv_bfloat162 t = __floats2bfloat162_rn(a, b);
    return *reinterpret_cast<uint32_t*>(&t);
}

// ---------------- fp32 -> bf16 hi/lo split ----------------
__global__ void split_bf16(const float* __restrict__ x,
                           __nv_bfloat16* __restrict__ hi,
                           __nv_bfloat16* __restrict__ lo, int n4)
{
    int i = blockIdx.x * blockDim.x + threadIdx.x;
    if (i >= n4) return;
    float4 v = ((const float4*)x)[i];
    float f[4] = {v.x, v.y, v.z, v.w};
    __nv_bfloat162 h2[2], l2[2];
    #pragma unroll
    for (int j = 0; j < 4; j++) {
        __nv_bfloat16 h = __float2bfloat16(f[j]);
        __nv_bfloat16 l = __float2bfloat16(f[j] - __bfloat162float(h));
        if (j & 1) { h2[j >> 1].y = h; l2[j >> 1].y = l; }
        else       { h2[j >> 1].x = h; l2[j >> 1].x = l; }
    }
    ((__nv_bfloat162*)hi)[2 * i]     = h2[0];
    ((__nv_bfloat162*)hi)[2 * i + 1] = h2[1];
    ((__nv_bfloat162*)lo)[2 * i]     = l2[0];
    ((__nv_bfloat162*)lo)[2 * i + 1] = l2[1];
}

// ---------------------------------------------------------------------------
// bf16x3 GEMM via mma.sync: C[M,N] = A[M,K] * B[N,K]^T
// CTA 128x256, BK=64, 8 warps (2M x 4N), 2-stage cp.async.
// GRID: blockIdx.x = M-block (fast-varying) so consecutive CTAs share the
// B panel (L2-resident) and stream A — minimizes DRAM traffic.
// ---------------------------------------------------------------------------
#define BM 128
#define BN 256
#define BK 64
#define STAGE_BYTES 98304   // Ah 16K | Al 16K | Bh 32K | Bl 32K
#define GEMM_SMEM (2 * STAGE_BYTES)

__global__ __launch_bounds__(256, 1) void gemm_bf16x3(
    const __nv_bfloat16* __restrict__ Ah, const __nv_bfloat16* __restrict__ Al,
    const __nv_bfloat16* __restrict__ Bh, const __nv_bfloat16* __restrict__ Bl,
    float* __restrict__ C, int M, int N, int K)
{
    extern __shared__ char smem[];
    const uint32_t sb = smem_u32(smem);
    const int tid  = threadIdx.x;
    const int wid  = tid >> 5;
    const int lane = tid & 31;
    const int wm = wid & 1;         // 2 M groups of 64
    const int wn = wid >> 1;        // 4 N groups of 64
    const int bm = blockIdx.x * BM;   // M fast-varying across CTA ids
    const int bn = blockIdx.y * BN;   // N panel slow-varying
    const int NC = K / BK;

    const __nv_bfloat16* gA[2] = {Ah + (size_t)bm * K, Al + (size_t)bm * K};
    const __nv_bfloat16* gB[2] = {Bh + (size_t)bn * K, Bl + (size_t)bn * K};

    const int lr0 = tid >> 3;       // 0..31
    const int lc  = tid & 7;

    auto load_chunk = [&](int ic, int s) {
        const uint32_t st = sb + s * STAGE_BYTES;
        const size_t k0 = (size_t)ic * BK;
        #pragma unroll
        for (int it = 0; it < 4; it++) {        // A: 128 rows, hi+lo
            int r = lr0 + it * 32;
            uint32_t off = SWZ((uint32_t)(r * 128 + lc * 16));
            size_t g = (size_t)r * K + k0 + lc * 8;
            CP16(st + off,         gA[0] + g);
            CP16(st + 16384 + off, gA[1] + g);
        }
        #pragma unroll
        for (int it = 0; it < 8; it++) {        // B: 256 rows, hi+lo
            int r = lr0 + it * 32;
            uint32_t off = SWZ((uint32_t)(r * 128 + lc * 16));
            size_t g = (size_t)r * K + k0 + lc * 8;
            CP16(st + 32768 + off, gB[0] + g);
            CP16(st + 65536 + off, gB[1] + g);
        }
        CP_COMMIT();
    };

    float acc[4][8][4];
    #pragma unroll
    for (int m = 0; m < 4; m++)
        #pragma unroll
        for (int n = 0; n < 8; n++)
            #pragma unroll
            for (int v = 0; v < 4; v++) acc[m][n][v] = 0.f;

    load_chunk(0, 0);
    load_chunk(1, 1);

    const int a_row = wm * 64 + (lane & 15);
    const int a_kb  = (lane >> 4) << 4;
    const int b_row = wn * 64 + (lane & 7) + ((lane >> 4) << 3);
    const int b_kb  = ((lane >> 3) & 1) << 4;

    for (int ic = 0; ic < NC; ic++) {
        const int s = ic & 1;
        if (ic == NC - 1) CP_WAIT0(); else CP_WAIT1();
        __syncthreads();

        const uint32_t st = sb + s * STAGE_BYTES;

        #pragma unroll
        for (int ks = 0; ks < 4; ks++) {
            uint32_t a[2][4][4];   // [split][mtile][reg]
            #pragma unroll
            for (int m = 0; m < 4; m++) {
                uint32_t off = SWZ((uint32_t)((a_row + m * 16) * 128 + ks * 32 + a_kb));
                LDSM4(a[0][m][0], a[0][m][1], a[0][m][2], a[0][m][3], st + off);
                LDSM4(a[1][m][0], a[1][m][1], a[1][m][2], a[1][m][3], st + 16384 + off);
            }
            #pragma unroll
            for (int p = 0; p < 4; p++) {
                uint32_t off = SWZ((uint32_t)((b_row + p * 16) * 128 + ks * 32 + b_kb));
                uint32_t bH[4], bL[4];
                LDSM4(bH[0], bH[1], bH[2], bH[3], st + 32768 + off);
                LDSM4(bL[0], bL[1], bL[2], bL[3], st + 65536 + off);
                #pragma unroll
                for (int m = 0; m < 4; m++) {
                    mma_bf16(acc[m][2*p],   a[0][m], bH[0], bH[1]);
                    mma_bf16(acc[m][2*p],   a[0][m], bL[0], bL[1]);
                    mma_bf16(acc[m][2*p],   a[1][m], bH[0], bH[1]);
                    mma_bf16(acc[m][2*p+1], a[0][m], bH[2], bH[3]);
                    mma_bf16(acc[m][2*p+1], a[0][m], bL[2], bL[3]);
                    mma_bf16(acc[m][2*p+1], a[1][m], bH[2], bH[3]);
                }
            }
        }
        __syncthreads();
        if (ic + 2 < NC) load_chunk(ic + 2, s);
    }

    const int er = lane >> 2;
    const int ec = (lane & 3) * 2;
    #pragma unroll
    for (int m = 0; m < 4; m++) {
        int row0 = bm + wm * 64 + m * 16 + er;
        #pragma unroll
        for (int n = 0; n < 8; n++) {
            int col = bn + wn * 64 + n * 8 + ec;
            *(float2*)(C + (size_t)row0 * N + col)       = make_float2(acc[m][n][0], acc[m][n][1]);
            *(float2*)(C + (size_t)(row0 + 8) * N + col) = make_float2(acc[m][n][2], acc[m][n][3]);
        }
    }
}

// ---------------- cos/sin table ----------------
__global__ void rope_table(float* __restrict__ ct, float* __restrict__ st)
{
    int idx = blockIdx.x * blockDim.x + threadIdx.x;
    if (idx >= L_ * 64) return;
    int l = idx >> 6, i = idx & 63;
    const double LN1E4_OVER_64 = 0.14391156831212787;
    double invf = exp(-(double)i * LN1E4_OVER_64);
    double ang  = (double)l * invf;
    const double TWO_PI = 6.283185307179586476925286766559;
    ang -= TWO_PI * floor(ang / TWO_PI);
    float s, c;
    sincosf((float)ang, &s, &c);
    ct[idx] = c; st[idx] = s;
}

// ---------------------------------------------------------------------------
// Fused RoPE + bf16 hi/lo split + relayout (unchanged, known-good)
// ---------------------------------------------------------------------------
__global__ __launch_bounds__(256) void qkv_split(
    const float* __restrict__ qkv,
    const float* __restrict__ ct, const float* __restrict__ st,
    __nv_bfloat16* __restrict__ qh, __nv_bfloat16* __restrict__ ql,
    __nv_bfloat16* __restrict__ kh, __nv_bfloat16* __restrict__ kl,
    __nv_bfloat16* __restrict__ vth, __nv_bfloat16* __restrict__ vtl)
{
    __shared__ float vtile[32][129];
    const int bh = blockIdx.y;
    const int b = bh >> 4, h = bh & 15;
    const int l0 = blockIdx.x * 32;
    const int tid = threadIdx.x;
    const int lane = tid & 31;
    const int hd0 = lane * 4;

    #pragma unroll
    for (int pass = 0; pass < 4; pass++) {
        int ll = (tid >> 5) + pass * 8;
        int l  = l0 + ll;
        size_t rowbase = (size_t)(b * L_ + l) * E3_ + h * HD_ + hd0;
        int i0 = hd0 >> 1;
        float c0 = ct[l * 64 + i0],     s0 = st[l * 64 + i0];
        float c1 = ct[l * 64 + i0 + 1], s1 = st[l * 64 + i0 + 1];

        float4 fq = *(const float4*)(qkv + rowbase);
        float q0 = fq.x * c0 - fq.y * s0, q1 = fq.y * c0 + fq.x * s0;
        float q2 = fq.z * c1 - fq.w * s1, q3 = fq.w * c1 + fq.z * s1;
        size_t o = (size_t)(bh * L_ + l) * HD_ + hd0;
        {
            __nv_bfloat16 h0 = __float2bfloat16(q0), h1 = __float2bfloat16(q1);
            __nv_bfloat16 h2 = __float2bfloat16(q2), h3 = __float2bfloat16(q3);
            *(__nv_bfloat162*)(qh + o)     = __nv_bfloat162(h0, h1);
            *(__nv_bfloat162*)(qh + o + 2) = __nv_bfloat162(h2, h3);
            *(__nv_bfloat162*)(ql + o)     = __floats2bfloat162_rn(q0 - __bfloat162float(h0), q1 - __bfloat162float(h1));
            *(__nv_bfloat162*)(ql + o + 2) = __floats2bfloat162_rn(q2 - __bfloat162float(h2), q3 - __bfloat162float(h3));
        }
        float4 fk = *(const float4*)(qkv + rowbase + D_);
        float k0v = fk.x * c0 - fk.y * s0, k1v = fk.y * c0 + fk.x * s0;
        float k2v = fk.z * c1 - fk.w * s1, k3v = fk.w * c1 + fk.z * s1;
        {
            __nv_bfloat16 h0 = __float2bfloat16(k0v), h1 = __float2bfloat16(k1v);
            __nv_bfloat16 h2 = __float2bfloat16(k2v), h3 = __float2bfloat16(k3v);
            *(__nv_bfloat162*)(kh + o)     = __nv_bfloat162(h0, h1);
            *(__nv_bfloat162*)(kh + o + 2) = __nv_bfloat162(h2, h3);
            *(__nv_bfloat162*)(kl + o)     = __floats2bfloat162_rn(k0v - __bfloat162float(h0), k1v - __bfloat162float(h1));
            *(__nv_bfloat162*)(kl + o + 2) = __floats2bfloat162_rn(k2v - __bfloat162float(h2), k3v - __bfloat162float(h3));
        }
        float4 fv = *(const float4*)(qkv + rowbase + 2 * D_);
        vtile[ll][hd0] = fv.x; vtile[ll][hd0 + 1] = fv.y;
        vtile[ll][hd0 + 2] = fv.z; vtile[ll][hd0 + 3] = fv.w;
    }
    __syncthreads();

    const int r = tid >> 1;
    const int lh = (tid & 1) * 16;
    size_t vbase = (size_t)(bh * HD_ + r) * L_ + l0 + lh;
    #pragma unroll
    for (int j = 0; j < 16; j += 2) {
        float f0 = vtile[lh + j][r], f1 = vtile[lh + j + 1][r];
        __nv_bfloat16 h0 = __float2bfloat16(f0), h1 = __float2bfloat16(f1);
        *(__nv_bfloat162*)(vth + vbase + j) = __nv_bfloat162(h0, h1);
        *(__nv_bfloat162*)(vtl + vbase + j) =
            __floats2bfloat162_rn(f0 - __bfloat162float(h0), f1 - __bfloat162float(h1));
    }
}

// ---------------------------------------------------------------------------
// Flash attention, bf16x3 mma.sync (unchanged from 2556us baseline).
// ---------------------------------------------------------------------------
#define ATT_SMEM 196608

__global__ __launch_bounds__(256, 1) void flash_mma(
    const __nv_bfloat16* __restrict__ qh, const __nv_bfloat16* __restrict__ ql,
    const __nv_bfloat16* __restrict__ kh, const __nv_bfloat16* __restrict__ kl,
    const __nv_bfloat16* __restrict__ vth, const __nv_bfloat16* __restrict__ vtl,
    __nv_bfloat16* __restrict__ yh, __nv_bfloat16* __restrict__ yl)
{
    extern __shared__ char smem[];
    const uint32_t sb = smem_u32(smem);
    const int tid = threadIdx.x, wid = tid >> 5, lane = tid & 31;
    const int bh = blockIdx.y;
    const int b = bh >> 4, h = bh & 15;
    const int q0 = (gridDim.x - 1 - blockIdx.x) * 128;   // heavy blocks first
    const int NB = q0 / 64 + 2;

    const size_t qkbase = (size_t)bh * L_ * HD_;
    const size_t vbase  = (size_t)bh * HD_ * L_;

    #pragma unroll
    for (int it = 0; it < 16; it++) {
        int idx = tid + 256 * it;
        int c = idx & 15, r = (idx >> 4) & 127, sp = idx >> 11;
        const __nv_bfloat16* src = (sp ? ql : qh) + qkbase + (size_t)(q0 + r) * 128 + c * 8;
        CP16(sb + sp * 32768 + (c >> 3) * 16384 + SWZ((uint32_t)(r * 128 + (c & 7) * 16)), src);
    }
    auto load_kv = [&](int kb, int s) {
        const uint32_t st0 = sb + 65536 + s * 65536;
        const int k0 = kb * 64;
        #pragma unroll
        for (int it = 0; it < 8; it++) {
            int idx = tid + 256 * it;
            int c = idx & 15, r = (idx >> 4) & 63, sp = idx >> 10;
            const __nv_bfloat16* src = (sp ? kl : kh) + qkbase + (size_t)(k0 + r) * 128 + c * 8;
            CP16(st0 + sp * 16384 + (c >> 3) * 8192 + SWZ((uint32_t)(r * 128 + (c & 7) * 16)), src);
        }
        #pragma unroll
        for (int it = 0; it < 8; it++) {
            int idx = tid + 256 * it;
            int c = idx & 7, r = (idx >> 3) & 127, sp = idx >> 10;
            const __nv_bfloat16* src = (sp ? vtl : vth) + vbase + (size_t)r * L_ + k0 + c * 8;
            CP16(st0 + 32768 + sp * 16384 + SWZ((uint32_t)(r * 128 + c * 16)), src);
        }
        CP_COMMIT();
    };

    load_kv(0, 0);
    load_kv(1, 1);

    float o[16][4];
    #pragma unroll
    for (int n = 0; n < 16; n++)
        #pragma unroll
        for (int v = 0; v < 4; v++) o[n][v] = 0.f;
    float m0 = -1e30f, m1 = -1e30f, l0 = 0.f, l1 = 0.f;

    const int a_row = wid * 16 + (lane & 15);
    const uint32_t a_kb = (lane >> 4) << 4;
    const int b_row = (lane & 7) + ((lane >> 4) << 3);
    const uint32_t b_kb = ((lane >> 3) & 1) << 4;
    const float scale = 0.08838834764831845f;
    const int row0 = q0 + wid * 16 + (lane >> 2);
    const int ec = (lane & 3) * 2;

    for (int kb = 0; kb < NB; kb++) {
        const int s = kb & 1;
        if (kb == NB - 1) CP_WAIT0(); else CP_WAIT1();
        __syncthreads();
        const uint32_t st0 = sb + 65536 + s * 65536;
        const int k0 = kb * 64;

        float sc[8][4];
        #pragma unroll
        for (int n = 0; n < 8; n++)
            #pragma unroll
            for (int v = 0; v < 4; v++) sc[n][v] = 0.f;

        #pragma unroll
        for (int half = 0; half < 2; half++)
            #pragma unroll
            for (int ks = 0; ks < 4; ks++) {
                uint32_t qo = sb + half * 16384 + SWZ((uint32_t)(a_row * 128 + ks * 32 + a_kb));
                uint32_t aH[4], aL[4];
                LDSM4(aH[0], aH[1], aH[2], aH[3], qo);
                LDSM4(aL[0], aL[1], aL[2], aL[3], qo + 32768);
                #pragma unroll
                for (int p = 0; p < 4; p++) {
                    uint32_t ko = st0 + half * 8192 + SWZ((uint32_t)((b_row + p * 16) * 128 + ks * 32 + b_kb));
                    uint32_t bH[4], bL[4];
                    LDSM4(bH[0], bH[1], bH[2], bH[3], ko);
                    LDSM4(bL[0], bL[1], bL[2], bL[3], ko + 16384);
                    mma_bf16(sc[2*p],   aH, bH[0], bH[1]);
                    mma_bf16(sc[2*p],   aH, bL[0], bL[1]);
                    mma_bf16(sc[2*p],   aL, bH[0], bH[1]);
                    mma_bf16(sc[2*p+1], aH, bH[2], bH[3]);
                    mma_bf16(sc[2*p+1], aH, bL[2], bL[3]);
                    mma_bf16(sc[2*p+1], aL, bH[2], bH[3]);
                }
            }

        const bool need_mask = (kb >= NB - 2);
        #pragma unroll
        for (int n = 0; n < 8; n++)
            #pragma unroll
            for (int v = 0; v < 4; v++) {
                float val = sc[n][v] * scale;
                if (need_mask) {
                    int col = k0 + n * 8 + ec + (v & 1);
                    int row = row0 + ((v >= 2) ? 8 : 0);
                    if (col > row) val = -1e30f;
                }
                sc[n][v] = val;
            }

        float mx0 = -1e30f, mx1 = -1e30f;
        #pragma unroll
        for (int n = 0; n < 8; n++) {
            mx0 = fmaxf(mx0, fmaxf(sc[n][0], sc[n][1]));
            mx1 = fmaxf(mx1, fmaxf(sc[n][2], sc[n][3]));
        }
        mx0 = fmaxf(mx0, __shfl_xor_sync(0xffffffffu, mx0, 1));
        mx0 = fmaxf(mx0, __shfl_xor_sync(0xffffffffu, mx0, 2));
        mx1 = fmaxf(mx1, __shfl_xor_sync(0xffffffffu, mx1, 1));
        mx1 = fmaxf(mx1, __shfl_xor_sync(0xffffffffu, mx1, 2));
        float nm0 = fmaxf(m0, mx0), nm1 = fmaxf(m1, mx1);
        float al0 = __expf(m0 - nm0), al1 = __expf(m1 - nm1);
        m0 = nm0; m1 = nm1;
        float ps0 = 0.f, ps1 = 0.f;
        #pragma unroll
        for (int n = 0; n < 8; n++) {
            float p0 = __expf(sc[n][0] - m0), p1 = __expf(sc[n][1] - m0);
            float p2 = __expf(sc[n][2] - m1), p3 = __expf(sc[n][3] - m1);
            sc[n][0] = p0; sc[n][1] = p1; sc[n][2] = p2; sc[n][3] = p3;
            ps0 += p0 + p1; ps1 += p2 + p3;
        }
        l0 = l0 * al0 + ps0;
        l1 = l1 * al1 + ps1;
        #pragma unroll
        for (int n = 0; n < 16; n++) {
            o[n][0] *= al0; o[n][1] *= al0; o[n][2] *= al1; o[n][3] *= al1;
        }

        #pragma unroll
        for (int kc = 0; kc < 4; kc++) {
            uint32_t aPh[4], aPl[4];
            {
                float p00 = sc[2*kc][0],   p01 = sc[2*kc][1],   p02 = sc[2*kc][2],   p03 = sc[2*kc][3];
                float p10 = sc[2*kc+1][0], p11 = sc[2*kc+1][1], p12 = sc[2*kc+1][2], p13 = sc[2*kc+1][3];
                aPh[0] = pack_bf16(p00, p01); aPh[1] = pack_bf16(p02, p03);
                aPh[2] = pack_bf16(p10, p11); aPh[3] = pack_bf16(p12, p13);
                __nv_bfloat162* hp = (__nv_bfloat162*)aPh;
                aPl[0] = pack_bf16(p00 - __bfloat162float(hp[0].x), p01 - __bfloat162float(hp[0].y));
                aPl[1] = pack_bf16(p02 - __bfloat162float(hp[1].x), p03 - __bfloat162float(hp[1].y));
                aPl[2] = pack_bf16(p10 - __bfloat162float(hp[2].x), p11 - __bfloat162float(hp[2].y));
                aPl[3] = pack_bf16(p12 - __bfloat162float(hp[3].x), p13 - __bfloat162float(hp[3].y));
            }
            #pragma unroll
            for (int p = 0; p < 8; p++) {
                uint32_t vo = st0 + 32768 + SWZ((uint32_t)((b_row + p * 16) * 128 + kc * 32 + b_kb));
                uint32_t bH[4], bL[4];
                LDSM4(bH[0], bH[1], bH[2], bH[3], vo);
                LDSM4(bL[0], bL[1], bL[2], bL[3], vo + 16384);
                mma_bf16(o[2*p],   aPh, bH[0], bH[1]);
                mma_bf16(o[2*p],   aPh, bL[0], bL[1]);
                mma_bf16(o[2*p],   aPl, bH[0], bH[1]);
                mma_bf16(o[2*p+1], aPh, bH[2], bH[3]);
                mma_bf16(o[2*p+1], aPh, bL[2], bL[3]);
                mma_bf16(o[2*p+1], aPl, bH[2], bH[3]);
            }
        }
        __syncthreads();
        if (kb + 2 < NB) load_kv(kb + 2, s);
    }

    l0 += __shfl_xor_sync(0xffffffffu, l0, 1);
    l0 += __shfl_xor_sync(0xffffffffu, l0, 2);
    l1 += __shfl_xor_sync(0xffffffffu, l1, 1);
    l1 += __shfl_xor_sync(0xffffffffu, l1, 2);
    float i0 = 1.f / l0, i1 = 1.f / l1;
    const size_t rbase = (size_t)(b * L_ + row0) * D_ + h * HD_ + ec;
    #pragma unroll
    for (int n = 0; n < 16; n++) {
        float v0 = o[n][0] * i0, v1 = o[n][1] * i0;
        float v2 = o[n][2] * i1, v3 = o[n][3] * i1;
        size_t o0 = rbase + n * 8;
        size_t o1 = o0 + 8 * (size_t)D_;
        __nv_bfloat16 h0 = __float2bfloat16(v0), h1 = __float2bfloat16(v1);
        __nv_bfloat16 h2 = __float2bfloat16(v2), h3 = __float2bfloat16(v3);
        *(__nv_bfloat162*)(yh + o0) = __nv_bfloat162(h0, h1);
        *(__nv_bfloat162*)(yh + o1) = __nv_bfloat162(h2, h3);
        *(__nv_bfloat162*)(yl + o0) = __floats2bfloat162_rn(v0 - __bfloat162float(h0), v1 - __bfloat162float(h1));
        *(__nv_bfloat162*)(yl + o1) = __floats2bfloat162_rn(v2 - __bfloat162float(h2), v3 - __bfloat162float(h3));
    }
}

// ---------------------------------------------------------------------------
extern "C" void kernel_launch(void* const* d_in, const int* in_sizes, int n_in,
                              void* d_out, int out_size)
{
    const float* x     = (const float*)d_in[0];
    const float* w_qkv = (const float*)d_in[1];
    const float* w_o   = (const float*)d_in[2];
    float* out = (float*)d_out;

    float *qkv, *ct, *st;
    __nv_bfloat16 *xh, *xl, *wqh, *wql, *woh, *wol, *yh, *yl;
    __nv_bfloat16 *qh, *ql, *kh, *kl, *vth, *vtl;
    cudaGetSymbolAddress((void**)&qkv, g_qkv);
    cudaGetSymbolAddress((void**)&ct,  g_cos); cudaGetSymbolAddress((void**)&st, g_sin);
    cudaGetSymbolAddress((void**)&xh,  g_xh);  cudaGetSymbolAddress((void**)&xl, g_xl);
    cudaGetSymbolAddress((void**)&wqh, g_wqh); cudaGetSymbolAddress((void**)&wql, g_wql);
    cudaGetSymbolAddress((void**)&woh, g_woh); cudaGetSymbolAddress((void**)&wol, g_wol);
    cudaGetSymbolAddress((void**)&yh,  g_yh);  cudaGetSymbolAddress((void**)&yl, g_yl);
    cudaGetSymbolAddress((void**)&qh,  g_qh);  cudaGetSymbolAddress((void**)&ql, g_ql);
    cudaGetSymbolAddress((void**)&kh,  g_kh);  cudaGetSymbolAddress((void**)&kl, g_kl);
    cudaGetSymbolAddress((void**)&vth, g_vth); cudaGetSymbolAddress((void**)&vtl, g_vtl);

    cudaFuncSetAttribute(gemm_bf16x3, cudaFuncAttributeMaxDynamicSharedMemorySize, GEMM_SMEM);
    cudaFuncSetAttribute(flash_mma,   cudaFuncAttributeMaxDynamicSharedMemorySize, ATT_SMEM);

    // splits + rope table
    split_bf16<<<(M_ * D_ / 4) / 256, 256>>>(x, xh, xl, M_ * D_ / 4);
    split_bf16<<<(E3_ * D_ / 4) / 256, 256>>>(w_qkv, wqh, wql, E3_ * D_ / 4);
    split_bf16<<<(D_ * D_ / 4) / 256, 256>>>(w_o, woh, wol, D_ * D_ / 4);
    rope_table<<<(L_ * 64) / 256, 256>>>(ct, st);

    // 1) qkv = x @ w_qkv^T   (grid: M fast-varying, N panels slow)
    gemm_bf16x3<<<dim3(M_ / BM, E3_ / BN), 256, GEMM_SMEM>>>(xh, xl, wqh, wql, qkv, M_, E3_, D_);

    // 2) fused rope + split + relayout
    qkv_split<<<dim3(L_ / 32, B_ * H_), 256>>>(qkv, ct, st, qh, ql, kh, kl, vth, vtl);

    // 3) causal flash attention (bf16x3 mma) -> yh/yl
    flash_mma<<<dim3(L_ / 128, B_ * H_), 256, ATT_SMEM>>>(qh, ql, kh, kl, vth, vtl, yh, yl);

    // 4) out = y @ w_o^T   (grid: M fast-varying)
    gemm_bf16x3<<<dim3(M_ / BM, D_ / BN), 256, GEMM_SMEM>>>(yh, yl, woh, wol, out, M_, D_, D_);
}

// round 8
// speedup vs baseline: 1.0027x; 1.0027x over previous
#include <cuda_runtime.h>
#include <cuda_bf16.h>
#include <math.h>
#include <stdint.h>

#define B_  4
#define L_  2048
#define D_  2048
#define H_  16
#define HD_ 128
#define M_  (B_ * L_)   // 8192
#define E3_ (3 * D_)    // 6144

// ---------------- scratch (allocation-free rule) ----------------
__device__ float g_qkv[(size_t)M_ * E3_];
__device__ __nv_bfloat16 g_xh[(size_t)M_ * D_], g_xl[(size_t)M_ * D_];
__device__ __nv_bfloat16 g_wqh[(size_t)E3_ * D_], g_wql[(size_t)E3_ * D_];
__device__ __nv_bfloat16 g_woh[(size_t)D_ * D_], g_wol[(size_t)D_ * D_];
__device__ __nv_bfloat16 g_yh[(size_t)M_ * D_], g_yl[(size_t)M_ * D_];
__device__ __nv_bfloat16 g_qh[(size_t)M_ * D_], g_ql[(size_t)M_ * D_];
__device__ __nv_bfloat16 g_kh[(size_t)M_ * D_], g_kl[(size_t)M_ * D_];
__device__ __nv_bfloat16 g_vth[(size_t)M_ * D_], g_vtl[(size_t)M_ * D_];
__device__ float g_cos[L_ * 64], g_sin[L_ * 64];

// ---------------- helpers ----------------
__device__ __forceinline__ uint32_t smem_u32(const void* p) {
    uint32_t a;
    asm("{ .reg .u64 t; cvta.to.shared.u64 t, %1; cvt.u32.u64 %0, t; }" : "=r"(a) : "l"(p));
    return a;
}
#define CP16(dst, src)  asm volatile("cp.async.cg.shared.global [%0], [%1], 16;" :: "r"(dst), "l"(src) : "memory")
#define CP_COMMIT()     asm volatile("cp.async.commit_group;" ::: "memory")
#define CP_WAIT0()      asm volatile("cp.async.wait_group 0;" ::: "memory")
#define CP_WAIT1()      asm volatile("cp.async.wait_group 1;" ::: "memory")
#define SWZ(o) ((o) ^ (((o) >> 3) & 0x70))

#define LDSM4(r0, r1, r2, r3, addr) \
    asm volatile("ldmatrix.sync.aligned.m8n8.x4.shared.b16 {%0,%1,%2,%3}, [%4];" \
        : "=r"(r0), "=r"(r1), "=r"(r2), "=r"(r3) : "r"(addr))

__device__ __forceinline__ void mma_bf16(float* c, const uint32_t* a, uint32_t b0, uint32_t b1) {
    asm volatile(
        "mma.sync.aligned.m16n8k16.row.col.f32.bf16.bf16.f32 "
        "{%0,%1,%2,%3}, {%4,%5,%6,%7}, {%8,%9}, {%0,%1,%2,%3};"
        : "+f"(c[0]), "+f"(c[1]), "+f"(c[2]), "+f"(c[3])
        : "r"(a[0]), "r"(a[1]), "r"(a[2]), "r"(a[3]), "r"(b0), "r"(b1));
}

__device__ __forceinline__ uint32_t pack_bf16(float a, float b) {
    __nv_bfloat162 t = __floats2bfloat162_rn(a, b);
    return *reinterpret_cast<uint32_t*>(&t);
}

// ---------------- fp32 -> bf16 hi/lo split ----------------
__global__ void split_bf16(const float* __restrict__ x,
                           __nv_bfloat16* __restrict__ hi,
                           __nv_bfloat16* __restrict__ lo, int n4)
{
    int i = blockIdx.x * blockDim.x + threadIdx.x;
    if (i >= n4) return;
    float4 v = ((const float4*)x)[i];
    float f[4] = {v.x, v.y, v.z, v.w};
    __nv_bfloat162 h2[2], l2[2];
    #pragma unroll
    for (int j = 0; j < 4; j++) {
        __nv_bfloat16 h = __float2bfloat16(f[j]);
        __nv_bfloat16 l = __float2bfloat16(f[j] - __bfloat162float(h));
        if (j & 1) { h2[j >> 1].y = h; l2[j >> 1].y = l; }
        else       { h2[j >> 1].x = h; l2[j >> 1].x = l; }
    }
    ((__nv_bfloat162*)hi)[2 * i]     = h2[0];
    ((__nv_bfloat162*)hi)[2 * i + 1] = h2[1];
    ((__nv_bfloat162*)lo)[2 * i]     = l2[0];
    ((__nv_bfloat162*)lo)[2 * i + 1] = l2[1];
}

// ---------------------------------------------------------------------------
// bf16x3 GEMM via mma.sync: C[M,N] = A[M,K] * B[N,K]^T
// CTA 128x256, BK=64, 8 warps (2M x 4N), 2-stage cp.async.
// GRID: blockIdx.x = M-block (fast-varying) so consecutive CTAs share the
// B panel (L2-resident) and stream A — minimizes DRAM traffic.
// ---------------------------------------------------------------------------
#define BM 128
#define BN 256
#define BK 64
#define STAGE_BYTES 98304   // Ah 16K | Al 16K | Bh 32K | Bl 32K
#define GEMM_SMEM (2 * STAGE_BYTES)

__global__ __launch_bounds__(256, 1) void gemm_bf16x3(
    const __nv_bfloat16* __restrict__ Ah, const __nv_bfloat16* __restrict__ Al,
    const __nv_bfloat16* __restrict__ Bh, const __nv_bfloat16* __restrict__ Bl,
    float* __restrict__ C, int M, int N, int K)
{
    extern __shared__ char smem[];
    const uint32_t sb = smem_u32(smem);
    const int tid  = threadIdx.x;
    const int wid  = tid >> 5;
    const int lane = tid & 31;
    const int wm = wid & 1;         // 2 M groups of 64
    const int wn = wid >> 1;        // 4 N groups of 64
    const int bm = blockIdx.x * BM;   // M fast-varying across CTA ids
    const int bn = blockIdx.y * BN;   // N panel slow-varying
    const int NC = K / BK;

    const __nv_bfloat16* gA[2] = {Ah + (size_t)bm * K, Al + (size_t)bm * K};
    const __nv_bfloat16* gB[2] = {Bh + (size_t)bn * K, Bl + (size_t)bn * K};

    const int lr0 = tid >> 3;       // 0..31
    const int lc  = tid & 7;

    auto load_chunk = [&](int ic, int s) {
        const uint32_t st = sb + s * STAGE_BYTES;
        const size_t k0 = (size_t)ic * BK;
        #pragma unroll
        for (int it = 0; it < 4; it++) {        // A: 128 rows, hi+lo
            int r = lr0 + it * 32;
            uint32_t off = SWZ((uint32_t)(r * 128 + lc * 16));
            size_t g = (size_t)r * K + k0 + lc * 8;
            CP16(st + off,         gA[0] + g);
            CP16(st + 16384 + off, gA[1] + g);
        }
        #pragma unroll
        for (int it = 0; it < 8; it++) {        // B: 256 rows, hi+lo
            int r = lr0 + it * 32;
            uint32_t off = SWZ((uint32_t)(r * 128 + lc * 16));
            size_t g = (size_t)r * K + k0 + lc * 8;
            CP16(st + 32768 + off, gB[0] + g);
            CP16(st + 65536 + off, gB[1] + g);
        }
        CP_COMMIT();
    };

    float acc[4][8][4];
    #pragma unroll
    for (int m = 0; m < 4; m++)
        #pragma unroll
        for (int n = 0; n < 8; n++)
            #pragma unroll
            for (int v = 0; v < 4; v++) acc[m][n][v] = 0.f;

    load_chunk(0, 0);
    load_chunk(1, 1);

    const int a_row = wm * 64 + (lane & 15);
    const int a_kb  = (lane >> 4) << 4;
    const int b_row = wn * 64 + (lane & 7) + ((lane >> 4) << 3);
    const int b_kb  = ((lane >> 3) & 1) << 4;

    for (int ic = 0; ic < NC; ic++) {
        const int s = ic & 1;
        if (ic == NC - 1) CP_WAIT0(); else CP_WAIT1();
        __syncthreads();

        const uint32_t st = sb + s * STAGE_BYTES;

        #pragma unroll
        for (int ks = 0; ks < 4; ks++) {
            uint32_t a[2][4][4];   // [split][mtile][reg]
            #pragma unroll
            for (int m = 0; m < 4; m++) {
                uint32_t off = SWZ((uint32_t)((a_row + m * 16) * 128 + ks * 32 + a_kb));
                LDSM4(a[0][m][0], a[0][m][1], a[0][m][2], a[0][m][3], st + off);
                LDSM4(a[1][m][0], a[1][m][1], a[1][m][2], a[1][m][3], st + 16384 + off);
            }
            #pragma unroll
            for (int p = 0; p < 4; p++) {
                uint32_t off = SWZ((uint32_t)((b_row + p * 16) * 128 + ks * 32 + b_kb));
                uint32_t bH[4], bL[4];
                LDSM4(bH[0], bH[1], bH[2], bH[3], st + 32768 + off);
                LDSM4(bL[0], bL[1], bL[2], bL[3], st + 65536 + off);
                #pragma unroll
                for (int m = 0; m < 4; m++) {
                    mma_bf16(acc[m][2*p],   a[0][m], bH[0], bH[1]);
                    mma_bf16(acc[m][2*p],   a[0][m], bL[0], bL[1]);
                    mma_bf16(acc[m][2*p],   a[1][m], bH[0], bH[1]);
                    mma_bf16(acc[m][2*p+1], a[0][m], bH[2], bH[3]);
                    mma_bf16(acc[m][2*p+1], a[0][m], bL[2], bL[3]);
                    mma_bf16(acc[m][2*p+1], a[1][m], bH[2], bH[3]);
                }
            }
        }
        __syncthreads();
        if (ic + 2 < NC) load_chunk(ic + 2, s);
    }

    const int er = lane >> 2;
    const int ec = (lane & 3) * 2;
    #pragma unroll
    for (int m = 0; m < 4; m++) {
        int row0 = bm + wm * 64 + m * 16 + er;
        #pragma unroll
        for (int n = 0; n < 8; n++) {
            int col = bn + wn * 64 + n * 8 + ec;
            *(float2*)(C + (size_t)row0 * N + col)       = make_float2(acc[m][n][0], acc[m][n][1]);
            *(float2*)(C + (size_t)(row0 + 8) * N + col) = make_float2(acc[m][n][2], acc[m][n][3]);
        }
    }
}

// ---------------- cos/sin table ----------------
__global__ void rope_table(float* __restrict__ ct, float* __restrict__ st)
{
    int idx = blockIdx.x * blockDim.x + threadIdx.x;
    if (idx >= L_ * 64) return;
    int l = idx >> 6, i = idx & 63;
    const double LN1E4_OVER_64 = 0.14391156831212787;
    double invf = exp(-(double)i * LN1E4_OVER_64);
    double ang  = (double)l * invf;
    const double TWO_PI = 6.283185307179586476925286766559;
    ang -= TWO_PI * floor(ang / TWO_PI);
    float s, c;
    sincosf((float)ang, &s, &c);
    ct[idx] = c; st[idx] = s;
}

// ---------------------------------------------------------------------------
// Fused RoPE + bf16 hi/lo split + relayout (unchanged, known-good)
// ---------------------------------------------------------------------------
__global__ __launch_bounds__(256) void qkv_split(
    const float* __restrict__ qkv,
    const float* __restrict__ ct, const float* __restrict__ st,
    __nv_bfloat16* __restrict__ qh, __nv_bfloat16* __restrict__ ql,
    __nv_bfloat16* __restrict__ kh, __nv_bfloat16* __restrict__ kl,
    __nv_bfloat16* __restrict__ vth, __nv_bfloat16* __restrict__ vtl)
{
    __shared__ float vtile[32][129];
    const int bh = blockIdx.y;
    const int b = bh >> 4, h = bh & 15;
    const int l0 = blockIdx.x * 32;
    const int tid = threadIdx.x;
    const int lane = tid & 31;
    const int hd0 = lane * 4;

    #pragma unroll
    for (int pass = 0; pass < 4; pass++) {
        int ll = (tid >> 5) + pass * 8;
        int l  = l0 + ll;
        size_t rowbase = (size_t)(b * L_ + l) * E3_ + h * HD_ + hd0;
        int i0 = hd0 >> 1;
        float c0 = ct[l * 64 + i0],     s0 = st[l * 64 + i0];
        float c1 = ct[l * 64 + i0 + 1], s1 = st[l * 64 + i0 + 1];

        float4 fq = *(const float4*)(qkv + rowbase);
        float q0 = fq.x * c0 - fq.y * s0, q1 = fq.y * c0 + fq.x * s0;
        float q2 = fq.z * c1 - fq.w * s1, q3 = fq.w * c1 + fq.z * s1;
        size_t o = (size_t)(bh * L_ + l) * HD_ + hd0;
        {
            __nv_bfloat16 h0 = __float2bfloat16(q0), h1 = __float2bfloat16(q1);
            __nv_bfloat16 h2 = __float2bfloat16(q2), h3 = __float2bfloat16(q3);
            *(__nv_bfloat162*)(qh + o)     = __nv_bfloat162(h0, h1);
            *(__nv_bfloat162*)(qh + o + 2) = __nv_bfloat162(h2, h3);
            *(__nv_bfloat162*)(ql + o)     = __floats2bfloat162_rn(q0 - __bfloat162float(h0), q1 - __bfloat162float(h1));
            *(__nv_bfloat162*)(ql + o + 2) = __floats2bfloat162_rn(q2 - __bfloat162float(h2), q3 - __bfloat162float(h3));
        }
        float4 fk = *(const float4*)(qkv + rowbase + D_);
        float k0v = fk.x * c0 - fk.y * s0, k1v = fk.y * c0 + fk.x * s0;
        float k2v = fk.z * c1 - fk.w * s1, k3v = fk.w * c1 + fk.z * s1;
        {
            __nv_bfloat16 h0 = __float2bfloat16(k0v), h1 = __float2bfloat16(k1v);
            __nv_bfloat16 h2 = __float2bfloat16(k2v), h3 = __float2bfloat16(k3v);
            *(__nv_bfloat162*)(kh + o)     = __nv_bfloat162(h0, h1);
            *(__nv_bfloat162*)(kh + o + 2) = __nv_bfloat162(h2, h3);
            *(__nv_bfloat162*)(kl + o)     = __floats2bfloat162_rn(k0v - __bfloat162float(h0), k1v - __bfloat162float(h1));
            *(__nv_bfloat162*)(kl + o + 2) = __floats2bfloat162_rn(k2v - __bfloat162float(h2), k3v - __bfloat162float(h3));
        }
        float4 fv = *(const float4*)(qkv + rowbase + 2 * D_);
        vtile[ll][hd0] = fv.x; vtile[ll][hd0 + 1] = fv.y;
        vtile[ll][hd0 + 2] = fv.z; vtile[ll][hd0 + 3] = fv.w;
    }
    __syncthreads();

    const int r = tid >> 1;
    const int lh = (tid & 1) * 16;
    size_t vbase = (size_t)(bh * HD_ + r) * L_ + l0 + lh;
    #pragma unroll
    for (int j = 0; j < 16; j += 2) {
        float f0 = vtile[lh + j][r], f1 = vtile[lh + j + 1][r];
        __nv_bfloat16 h0 = __float2bfloat16(f0), h1 = __float2bfloat16(f1);
        *(__nv_bfloat162*)(vth + vbase + j) = __nv_bfloat162(h0, h1);
        *(__nv_bfloat162*)(vtl + vbase + j) =
            __floats2bfloat162_rn(f0 - __bfloat162float(h0), f1 - __bfloat162float(h1));
    }
}

// ---------------------------------------------------------------------------
// Flash attention, bf16x3 mma.sync (unchanged from 2556us baseline).
// ---------------------------------------------------------------------------
#define ATT_SMEM 196608

__global__ __launch_bounds__(256, 1) void flash_mma(
    const __nv_bfloat16* __restrict__ qh, const __nv_bfloat16* __restrict__ ql,
    const __nv_bfloat16* __restrict__ kh, const __nv_bfloat16* __restrict__ kl,
    const __nv_bfloat16* __restrict__ vth, const __nv_bfloat16* __restrict__ vtl,
    __nv_bfloat16* __restrict__ yh, __nv_bfloat16* __restrict__ yl)
{
    extern __shared__ char smem[];
    const uint32_t sb = smem_u32(smem);
    const int tid = threadIdx.x, wid = tid >> 5, lane = tid & 31;
    const int bh = blockIdx.y;
    const int b = bh >> 4, h = bh & 15;
    const int q0 = (gridDim.x - 1 - blockIdx.x) * 128;   // heavy blocks first
    const int NB = q0 / 64 + 2;

    const size_t qkbase = (size_t)bh * L_ * HD_;
    const size_t vbase  = (size_t)bh * HD_ * L_;

    #pragma unroll
    for (int it = 0; it < 16; it++) {
        int idx = tid + 256 * it;
        int c = idx & 15, r = (idx >> 4) & 127, sp = idx >> 11;
        const __nv_bfloat16* src = (sp ? ql : qh) + qkbase + (size_t)(q0 + r) * 128 + c * 8;
        CP16(sb + sp * 32768 + (c >> 3) * 16384 + SWZ((uint32_t)(r * 128 + (c & 7) * 16)), src);
    }
    auto load_kv = [&](int kb, int s) {
        const uint32_t st0 = sb + 65536 + s * 65536;
        const int k0 = kb * 64;
        #pragma unroll
        for (int it = 0; it < 8; it++) {
            int idx = tid + 256 * it;
            int c = idx & 15, r = (idx >> 4) & 63, sp = idx >> 10;
            const __nv_bfloat16* src = (sp ? kl : kh) + qkbase + (size_t)(k0 + r) * 128 + c * 8;
            CP16(st0 + sp * 16384 + (c >> 3) * 8192 + SWZ((uint32_t)(r * 128 + (c & 7) * 16)), src);
        }
        #pragma unroll
        for (int it = 0; it < 8; it++) {
            int idx = tid + 256 * it;
            int c = idx & 7, r = (idx >> 3) & 127, sp = idx >> 10;
            const __nv_bfloat16* src = (sp ? vtl : vth) + vbase + (size_t)r * L_ + k0 + c * 8;
            CP16(st0 + 32768 + sp * 16384 + SWZ((uint32_t)(r * 128 + c * 16)), src);
        }
        CP_COMMIT();
    };

    load_kv(0, 0);
    load_kv(1, 1);

    float o[16][4];
    #pragma unroll
    for (int n = 0; n < 16; n++)
        #pragma unroll
        for (int v = 0; v < 4; v++) o[n][v] = 0.f;
    float m0 = -1e30f, m1 = -1e30f, l0 = 0.f, l1 = 0.f;

    const int a_row = wid * 16 + (lane & 15);
    const uint32_t a_kb = (lane >> 4) << 4;
    const int b_row = (lane & 7) + ((lane >> 4) << 3);
    const uint32_t b_kb = ((lane >> 3) & 1) << 4;
    const float scale = 0.08838834764831845f;
    const int row0 = q0 + wid * 16 + (lane >> 2);
    const int ec = (lane & 3) * 2;

    for (int kb = 0; kb < NB; kb++) {
        const int s = kb & 1;
        if (kb == NB - 1) CP_WAIT0(); else CP_WAIT1();
        __syncthreads();
        const uint32_t st0 = sb + 65536 + s * 65536;
        const int k0 = kb * 64;

        float sc[8][4];
        #pragma unroll
        for (int n = 0; n < 8; n++)
            #pragma unroll
            for (int v = 0; v < 4; v++) sc[n][v] = 0.f;

        #pragma unroll
        for (int half = 0; half < 2; half++)
            #pragma unroll
            for (int ks = 0; ks < 4; ks++) {
                uint32_t qo = sb + half * 16384 + SWZ((uint32_t)(a_row * 128 + ks * 32 + a_kb));
                uint32_t aH[4], aL[4];
                LDSM4(aH[0], aH[1], aH[2], aH[3], qo);
                LDSM4(aL[0], aL[1], aL[2], aL[3], qo + 32768);
                #pragma unroll
                for (int p = 0; p < 4; p++) {
                    uint32_t ko = st0 + half * 8192 + SWZ((uint32_t)((b_row + p * 16) * 128 + ks * 32 + b_kb));
                    uint32_t bH[4], bL[4];
                    LDSM4(bH[0], bH[1], bH[2], bH[3], ko);
                    LDSM4(bL[0], bL[1], bL[2], bL[3], ko + 16384);
                    mma_bf16(sc[2*p],   aH, bH[0], bH[1]);
                    mma_bf16(sc[2*p],   aH, bL[0], bL[1]);
                    mma_bf16(sc[2*p],   aL, bH[0], bH[1]);
                    mma_bf16(sc[2*p+1], aH, bH[2], bH[3]);
                    mma_bf16(sc[2*p+1], aH, bL[2], bL[3]);
                    mma_bf16(sc[2*p+1], aL, bH[2], bH[3]);
                }
            }

        const bool need_mask = (kb >= NB - 2);
        #pragma unroll
        for (int n = 0; n < 8; n++)
            #pragma unroll
            for (int v = 0; v < 4; v++) {
                float val = sc[n][v] * scale;
                if (need_mask) {
                    int col = k0 + n * 8 + ec + (v & 1);
                    int row = row0 + ((v >= 2) ? 8 : 0);
                    if (col > row) val = -1e30f;
                }
                sc[n][v] = val;
            }

        float mx0 = -1e30f, mx1 = -1e30f;
        #pragma unroll
        for (int n = 0; n < 8; n++) {
            mx0 = fmaxf(mx0, fmaxf(sc[n][0], sc[n][1]));
            mx1 = fmaxf(mx1, fmaxf(sc[n][2], sc[n][3]));
        }
        mx0 = fmaxf(mx0, __shfl_xor_sync(0xffffffffu, mx0, 1));
        mx0 = fmaxf(mx0, __shfl_xor_sync(0xffffffffu, mx0, 2));
        mx1 = fmaxf(mx1, __shfl_xor_sync(0xffffffffu, mx1, 1));
        mx1 = fmaxf(mx1, __shfl_xor_sync(0xffffffffu, mx1, 2));
        float nm0 = fmaxf(m0, mx0), nm1 = fmaxf(m1, mx1);
        float al0 = __expf(m0 - nm0), al1 = __expf(m1 - nm1);
        m0 = nm0; m1 = nm1;
        float ps0 = 0.f, ps1 = 0.f;
        #pragma unroll
        for (int n = 0; n < 8; n++) {
            float p0 = __expf(sc[n][0] - m0), p1 = __expf(sc[n][1] - m0);
            float p2 = __expf(sc[n][2] - m1), p3 = __expf(sc[n][3] - m1);
            sc[n][0] = p0; sc[n][1] = p1; sc[n][2] = p2; sc[n][3] = p3;
            ps0 += p0 + p1; ps1 += p2 + p3;
        }
        l0 = l0 * al0 + ps0;
        l1 = l1 * al1 + ps1;
        #pragma unroll
        for (int n = 0; n < 16; n++) {
            o[n][0] *= al0; o[n][1] *= al0; o[n][2] *= al1; o[n][3] *= al1;
        }

        #pragma unroll
        for (int kc = 0; kc < 4; kc++) {
            uint32_t aPh[4], aPl[4];
            {
                float p00 = sc[2*kc][0],   p01 = sc[2*kc][1],   p02 = sc[2*kc][2],   p03 = sc[2*kc][3];
                float p10 = sc[2*kc+1][0], p11 = sc[2*kc+1][1], p12 = sc[2*kc+1][2], p13 = sc[2*kc+1][3];
                aPh[0] = pack_bf16(p00, p01); aPh[1] = pack_bf16(p02, p03);
                aPh[2] = pack_bf16(p10, p11); aPh[3] = pack_bf16(p12, p13);
                __nv_bfloat162* hp = (__nv_bfloat162*)aPh;
                aPl[0] = pack_bf16(p00 - __bfloat162float(hp[0].x), p01 - __bfloat162float(hp[0].y));
                aPl[1] = pack_bf16(p02 - __bfloat162float(hp[1].x), p03 - __bfloat162float(hp[1].y));
                aPl[2] = pack_bf16(p10 - __bfloat162float(hp[2].x), p11 - __bfloat162float(hp[2].y));
                aPl[3] = pack_bf16(p12 - __bfloat162float(hp[3].x), p13 - __bfloat162float(hp[3].y));
            }
            #pragma unroll
            for (int p = 0; p < 8; p++) {
                uint32_t vo = st0 + 32768 + SWZ((uint32_t)((b_row + p * 16) * 128 + kc * 32 + b_kb));
                uint32_t bH[4], bL[4];
                LDSM4(bH[0], bH[1], bH[2], bH[3], vo);
                LDSM4(bL[0], bL[1], bL[2], bL[3], vo + 16384);
                mma_bf16(o[2*p],   aPh, bH[0], bH[1]);
                mma_bf16(o[2*p],   aPh, bL[0], bL[1]);
                mma_bf16(o[2*p],   aPl, bH[0], bH[1]);
                mma_bf16(o[2*p+1], aPh, bH[2], bH[3]);
                mma_bf16(o[2*p+1], aPh, bL[2], bL[3]);
                mma_bf16(o[2*p+1], aPl, bH[2], bH[3]);
            }
        }
        __syncthreads();
        if (kb + 2 < NB) load_kv(kb + 2, s);
    }

    l0 += __shfl_xor_sync(0xffffffffu, l0, 1);
    l0 += __shfl_xor_sync(0xffffffffu, l0, 2);
    l1 += __shfl_xor_sync(0xffffffffu, l1, 1);
    l1 += __shfl_xor_sync(0xffffffffu, l1, 2);
    float i0 = 1.f / l0, i1 = 1.f / l1;
    const size_t rbase = (size_t)(b * L_ + row0) * D_ + h * HD_ + ec;
    #pragma unroll
    for (int n = 0; n < 16; n++) {
        float v0 = o[n][0] * i0, v1 = o[n][1] * i0;
        float v2 = o[n][2] * i1, v3 = o[n][3] * i1;
        size_t o0 = rbase + n * 8;
        size_t o1 = o0 + 8 * (size_t)D_;
        __nv_bfloat16 h0 = __float2bfloat16(v0), h1 = __float2bfloat16(v1);
        __nv_bfloat16 h2 = __float2bfloat16(v2), h3 = __float2bfloat16(v3);
        *(__nv_bfloat162*)(yh + o0) = __nv_bfloat162(h0, h1);
        *(__nv_bfloat162*)(yh + o1) = __nv_bfloat162(h2, h3);
        *(__nv_bfloat162*)(yl + o0) = __floats2bfloat162_rn(v0 - __bfloat162float(h0), v1 - __bfloat162float(h1));
        *(__nv_bfloat162*)(yl + o1) = __floats2bfloat162_rn(v2 - __bfloat162float(h2), v3 - __bfloat162float(h3));
    }
}

// ---------------------------------------------------------------------------
extern "C" void kernel_launch(void* const* d_in, const int* in_sizes, int n_in,
                              void* d_out, int out_size)
{
    const float* x     = (const float*)d_in[0];
    const float* w_qkv = (const float*)d_in[1];
    const float* w_o   = (const float*)d_in[2];
    float* out = (float*)d_out;

    float *qkv, *ct, *st;
    __nv_bfloat16 *xh, *xl, *wqh, *wql, *woh, *wol, *yh, *yl;
    __nv_bfloat16 *qh, *ql, *kh, *kl, *vth, *vtl;
    cudaGetSymbolAddress((void**)&qkv, g_qkv);
    cudaGetSymbolAddress((void**)&ct,  g_cos); cudaGetSymbolAddress((void**)&st, g_sin);
    cudaGetSymbolAddress((void**)&xh,  g_xh);  cudaGetSymbolAddress((void**)&xl, g_xl);
    cudaGetSymbolAddress((void**)&wqh, g_wqh); cudaGetSymbolAddress((void**)&wql, g_wql);
    cudaGetSymbolAddress((void**)&woh, g_woh); cudaGetSymbolAddress((void**)&wol, g_wol);
    cudaGetSymbolAddress((void**)&yh,  g_yh);  cudaGetSymbolAddress((void**)&yl, g_yl);
    cudaGetSymbolAddress((void**)&qh,  g_qh);  cudaGetSymbolAddress((void**)&ql, g_ql);
    cudaGetSymbolAddress((void**)&kh,  g_kh);  cudaGetSymbolAddress((void**)&kl, g_kl);
    cudaGetSymbolAddress((void**)&vth, g_vth); cudaGetSymbolAddress((void**)&vtl, g_vtl);

    cudaFuncSetAttribute(gemm_bf16x3, cudaFuncAttributeMaxDynamicSharedMemorySize, GEMM_SMEM);
    cudaFuncSetAttribute(flash_mma,   cudaFuncAttributeMaxDynamicSharedMemorySize, ATT_SMEM);

    // splits + rope table
    split_bf16<<<(M_ * D_ / 4) / 256, 256>>>(x, xh, xl, M_ * D_ / 4);
    split_bf16<<<(E3_ * D_ / 4) / 256, 256>>>(w_qkv, wqh, wql, E3_ * D_ / 4);
    split_bf16<<<(D_ * D_ / 4) / 256, 256>>>(w_o, woh, wol, D_ * D_ / 4);
    rope_table<<<(L_ * 64) / 256, 256>>>(ct, st);

    // 1) qkv = x @ w_qkv^T   (grid: M fast-varying, N panels slow)
    gemm_bf16x3<<<dim3(M_ / BM, E3_ / BN), 256, GEMM_SMEM>>>(xh, xl, wqh, wql, qkv, M_, E3_, D_);

    // 2) fused rope + split + relayout
    qkv_split<<<dim3(L_ / 32, B_ * H_), 256>>>(qkv, ct, st, qh, ql, kh, kl, vth, vtl);

    // 3) causal flash attention (bf16x3 mma) -> yh/yl
    flash_mma<<<dim3(L_ / 128, B_ * H_), 256, ATT_SMEM>>>(qh, ql, kh, kl, vth, vtl, yh, yl);

    // 4) out = y @ w_o^T   (grid: M fast-varying)
    gemm_bf16x3<<<dim3(M_ / BM, D_ / BN), 256, GEMM_SMEM>>>(yh, yl, woh, wol, out, M_, D_, D_);
}

// round 9
// speedup vs baseline: 1.3944x; 1.3907x over previous
#include <cuda_runtime.h>
#include <cuda_fp16.h>
#include <math.h>
#include <stdint.h>

#define B_  4
#define L_  2048
#define D_  2048
#define H_  16
#define HD_ 128
#define M_  (B_ * L_)   // 8192
#define E3_ (3 * D_)    // 6144

// ---------------- scratch (allocation-free rule) ----------------
__device__ float g_qkv[(size_t)M_ * E3_];
__device__ __half g_x16[(size_t)M_ * D_];
__device__ __half g_wqh[(size_t)E3_ * D_], g_wql[(size_t)E3_ * D_];
__device__ __half g_woh[(size_t)D_ * D_], g_wol[(size_t)D_ * D_];
__device__ __half g_y16[(size_t)M_ * D_];
__device__ __half g_q16[(size_t)M_ * D_];
__device__ __half g_kh[(size_t)M_ * D_], g_kl[(size_t)M_ * D_];
__device__ __half g_vth[(size_t)M_ * D_], g_vtl[(size_t)M_ * D_];
__device__ float g_cos[L_ * 64], g_sin[L_ * 64];

// ---------------- helpers ----------------
__device__ __forceinline__ uint32_t smem_u32(const void* p) {
    uint32_t a;
    asm("{ .reg .u64 t; cvta.to.shared.u64 t, %1; cvt.u32.u64 %0, t; }" : "=r"(a) : "l"(p));
    return a;
}
#define CP16(dst, src)  asm volatile("cp.async.cg.shared.global [%0], [%1], 16;" :: "r"(dst), "l"(src) : "memory")
#define CP_COMMIT()     asm volatile("cp.async.commit_group;" ::: "memory")
#define CP_WAIT0()      asm volatile("cp.async.wait_group 0;" ::: "memory")
#define CP_WAIT1()      asm volatile("cp.async.wait_group 1;" ::: "memory")
#define SWZ(o) ((o) ^ (((o) >> 3) & 0x70))

#define LDSM4(r0, r1, r2, r3, addr) \
    asm volatile("ldmatrix.sync.aligned.m8n8.x4.shared.b16 {%0,%1,%2,%3}, [%4];" \
        : "=r"(r0), "=r"(r1), "=r"(r2), "=r"(r3) : "r"(addr))

__device__ __forceinline__ void mma_f16(float* c, const uint32_t* a, uint32_t b0, uint32_t b1) {
    asm volatile(
        "mma.sync.aligned.m16n8k16.row.col.f32.f16.f16.f32 "
        "{%0,%1,%2,%3}, {%4,%5,%6,%7}, {%8,%9}, {%0,%1,%2,%3};"
        : "+f"(c[0]), "+f"(c[1]), "+f"(c[2]), "+f"(c[3])
        : "r"(a[0]), "r"(a[1]), "r"(a[2]), "r"(a[3]), "r"(b0), "r"(b1));
}

__device__ __forceinline__ uint32_t pack_f16(float a, float b) {
    __half2 t = __floats2half2_rn(a, b);
    return *reinterpret_cast<uint32_t*>(&t);
}

// ---------------- fp32 -> fp16 (plain) ----------------
__global__ void cvt_f16(const float* __restrict__ x, __half* __restrict__ o, int n4)
{
    int i = blockIdx.x * blockDim.x + threadIdx.x;
    if (i >= n4) return;
    float4 v = ((const float4*)x)[i];
    ((__half2*)o)[2 * i]     = __floats2half2_rn(v.x, v.y);
    ((__half2*)o)[2 * i + 1] = __floats2half2_rn(v.z, v.w);
}

// ---------------- fp32 -> fp16 hi/lo split ----------------
__global__ void split_f16(const float* __restrict__ x,
                          __half* __restrict__ hi, __half* __restrict__ lo, int n4)
{
    int i = blockIdx.x * blockDim.x + threadIdx.x;
    if (i >= n4) return;
    float4 v = ((const float4*)x)[i];
    float f[4] = {v.x, v.y, v.z, v.w};
    __half h[4], l[4];
    #pragma unroll
    for (int j = 0; j < 4; j++) {
        h[j] = __float2half_rn(f[j]);
        l[j] = __float2half_rn(f[j] - __half2float(h[j]));
    }
    ((__half2*)hi)[2 * i]     = __halves2half2(h[0], h[1]);
    ((__half2*)hi)[2 * i + 1] = __halves2half2(h[2], h[3]);
    ((__half2*)lo)[2 * i]     = __halves2half2(l[0], l[1]);
    ((__half2*)lo)[2 * i + 1] = __halves2half2(l[2], l[3]);
}

// ---------------------------------------------------------------------------
// fp16 x2 GEMM via mma.sync: C[M,N] = A[M,K] * B[N,K]^T
//   A plain fp16, B split hi/lo:  C = A*Bh + A*Bl   (2 MMAs per step)
// CTA 128x256, BK=64, 8 warps (2M x 4N), 2-stage cp.async.
// ---------------------------------------------------------------------------
#define BM 128
#define BN 256
#define BK 64
#define STG 81920   // A 16K | Bh 32K | Bl 32K
#define GEMM_SMEM (2 * STG)

__global__ __launch_bounds__(256, 1) void gemm_f16x2(
    const __half* __restrict__ A,
    const __half* __restrict__ Bh, const __half* __restrict__ Bl,
    float* __restrict__ C, int M, int N, int K)
{
    extern __shared__ char smem[];
    const uint32_t sb = smem_u32(smem);
    const int tid  = threadIdx.x;
    const int wid  = tid >> 5;
    const int lane = tid & 31;
    const int wm = wid & 1;
    const int wn = wid >> 1;
    const int bm = blockIdx.x * BM;
    const int bn = blockIdx.y * BN;
    const int NC = K / BK;

    const __half* gA  = A  + (size_t)bm * K;
    const __half* gBh = Bh + (size_t)bn * K;
    const __half* gBl = Bl + (size_t)bn * K;

    const int lr0 = tid >> 3;
    const int lc  = tid & 7;

    auto load_chunk = [&](int ic, int s) {
        const uint32_t st = sb + s * STG;
        const size_t k0 = (size_t)ic * BK;
        #pragma unroll
        for (int it = 0; it < 4; it++) {        // A: 128 rows
            int r = lr0 + it * 32;
            uint32_t off = SWZ((uint32_t)(r * 128 + lc * 16));
            CP16(st + off, gA + (size_t)r * K + k0 + lc * 8);
        }
        #pragma unroll
        for (int it = 0; it < 8; it++) {        // B: 256 rows, hi+lo
            int r = lr0 + it * 32;
            uint32_t off = SWZ((uint32_t)(r * 128 + lc * 16));
            size_t g = (size_t)r * K + k0 + lc * 8;
            CP16(st + 16384 + off, gBh + g);
            CP16(st + 49152 + off, gBl + g);
        }
        CP_COMMIT();
    };

    float acc[4][8][4];
    #pragma unroll
    for (int m = 0; m < 4; m++)
        #pragma unroll
        for (int n = 0; n < 8; n++)
            #pragma unroll
            for (int v = 0; v < 4; v++) acc[m][n][v] = 0.f;

    load_chunk(0, 0);
    load_chunk(1, 1);

    const int a_row = wm * 64 + (lane & 15);
    const int a_kb  = (lane >> 4) << 4;
    const int b_row = wn * 64 + (lane & 7) + ((lane >> 4) << 3);
    const int b_kb  = ((lane >> 3) & 1) << 4;

    for (int ic = 0; ic < NC; ic++) {
        const int s = ic & 1;
        if (ic == NC - 1) CP_WAIT0(); else CP_WAIT1();
        __syncthreads();

        const uint32_t st = sb + s * STG;

        #pragma unroll
        for (int ks = 0; ks < 4; ks++) {
            uint32_t a[4][4];
            #pragma unroll
            for (int m = 0; m < 4; m++) {
                uint32_t off = SWZ((uint32_t)((a_row + m * 16) * 128 + ks * 32 + a_kb));
                LDSM4(a[m][0], a[m][1], a[m][2], a[m][3], st + off);
            }
            #pragma unroll
            for (int p = 0; p < 4; p++) {
                uint32_t off = SWZ((uint32_t)((b_row + p * 16) * 128 + ks * 32 + b_kb));
                uint32_t bH[4], bL[4];
                LDSM4(bH[0], bH[1], bH[2], bH[3], st + 16384 + off);
                LDSM4(bL[0], bL[1], bL[2], bL[3], st + 49152 + off);
                #pragma unroll
                for (int m = 0; m < 4; m++) {
                    mma_f16(acc[m][2*p],   a[m], bH[0], bH[1]);
                    mma_f16(acc[m][2*p],   a[m], bL[0], bL[1]);
                    mma_f16(acc[m][2*p+1], a[m], bH[2], bH[3]);
                    mma_f16(acc[m][2*p+1], a[m], bL[2], bL[3]);
                }
            }
        }
        __syncthreads();
        if (ic + 2 < NC) load_chunk(ic + 2, s);
    }

    const int er = lane >> 2;
    const int ec = (lane & 3) * 2;
    #pragma unroll
    for (int m = 0; m < 4; m++) {
        int row0 = bm + wm * 64 + m * 16 + er;
        #pragma unroll
        for (int n = 0; n < 8; n++) {
            int col = bn + wn * 64 + n * 8 + ec;
            *(float2*)(C + (size_t)row0 * N + col)       = make_float2(acc[m][n][0], acc[m][n][1]);
            *(float2*)(C + (size_t)(row0 + 8) * N + col) = make_float2(acc[m][n][2], acc[m][n][3]);
        }
    }
}

// ---------------- cos/sin table ----------------
__global__ void rope_table(float* __restrict__ ct, float* __restrict__ st)
{
    int idx = blockIdx.x * blockDim.x + threadIdx.x;
    if (idx >= L_ * 64) return;
    int l = idx >> 6, i = idx & 63;
    const double LN1E4_OVER_64 = 0.14391156831212787;
    double invf = exp(-(double)i * LN1E4_OVER_64);
    double ang  = (double)l * invf;
    const double TWO_PI = 6.283185307179586476925286766559;
    ang -= TWO_PI * floor(ang / TWO_PI);
    float s, c;
    sincosf((float)ang, &s, &c);
    ct[idx] = c; st[idx] = s;
}

// ---------------------------------------------------------------------------
// Fused RoPE + fp16 conversion/split + relayout:
//   q -> plain fp16 [b,h,l,128]; k -> fp16 hi/lo [b,h,l,128];
//   v -> fp16 hi/lo transposed [b,h,128,l]
// ---------------------------------------------------------------------------
__global__ __launch_bounds__(256) void qkv_split(
    const float* __restrict__ qkv,
    const float* __restrict__ ct, const float* __restrict__ st,
    __half* __restrict__ q16,
    __half* __restrict__ kh, __half* __restrict__ kl,
    __half* __restrict__ vth, __half* __restrict__ vtl)
{
    __shared__ float vtile[32][129];
    const int bh = blockIdx.y;
    const int b = bh >> 4, h = bh & 15;
    const int l0 = blockIdx.x * 32;
    const int tid = threadIdx.x;
    const int lane = tid & 31;
    const int hd0 = lane * 4;

    #pragma unroll
    for (int pass = 0; pass < 4; pass++) {
        int ll = (tid >> 5) + pass * 8;
        int l  = l0 + ll;
        size_t rowbase = (size_t)(b * L_ + l) * E3_ + h * HD_ + hd0;
        int i0 = hd0 >> 1;
        float c0 = ct[l * 64 + i0],     s0 = st[l * 64 + i0];
        float c1 = ct[l * 64 + i0 + 1], s1 = st[l * 64 + i0 + 1];

        // q: plain fp16
        float4 fq = *(const float4*)(qkv + rowbase);
        float q0 = fq.x * c0 - fq.y * s0, q1 = fq.y * c0 + fq.x * s0;
        float q2 = fq.z * c1 - fq.w * s1, q3 = fq.w * c1 + fq.z * s1;
        size_t o = (size_t)(bh * L_ + l) * HD_ + hd0;
        *(__half2*)(q16 + o)     = __floats2half2_rn(q0, q1);
        *(__half2*)(q16 + o + 2) = __floats2half2_rn(q2, q3);

        // k: fp16 hi/lo
        float4 fk = *(const float4*)(qkv + rowbase + D_);
        float k0v = fk.x * c0 - fk.y * s0, k1v = fk.y * c0 + fk.x * s0;
        float k2v = fk.z * c1 - fk.w * s1, k3v = fk.w * c1 + fk.z * s1;
        {
            __half h0 = __float2half_rn(k0v), h1 = __float2half_rn(k1v);
            __half h2 = __float2half_rn(k2v), h3 = __float2half_rn(k3v);
            *(__half2*)(kh + o)     = __halves2half2(h0, h1);
            *(__half2*)(kh + o + 2) = __halves2half2(h2, h3);
            *(__half2*)(kl + o)     = __floats2half2_rn(k0v - __half2float(h0), k1v - __half2float(h1));
            *(__half2*)(kl + o + 2) = __floats2half2_rn(k2v - __half2float(h2), k3v - __half2float(h3));
        }
        // v -> smem for transpose
        float4 fv = *(const float4*)(qkv + rowbase + 2 * D_);
        vtile[ll][hd0] = fv.x; vtile[ll][hd0 + 1] = fv.y;
        vtile[ll][hd0 + 2] = fv.z; vtile[ll][hd0 + 3] = fv.w;
    }
    __syncthreads();

    const int r = tid >> 1;
    const int lh = (tid & 1) * 16;
    size_t vbase = (size_t)(bh * HD_ + r) * L_ + l0 + lh;
    #pragma unroll
    for (int j = 0; j < 16; j += 2) {
        float f0 = vtile[lh + j][r], f1 = vtile[lh + j + 1][r];
        __half h0 = __float2half_rn(f0), h1 = __float2half_rn(f1);
        *(__half2*)(vth + vbase + j) = __halves2half2(h0, h1);
        *(__half2*)(vtl + vbase + j) =
            __floats2half2_rn(f0 - __half2float(h0), f1 - __half2float(h1));
    }
}

// ---------------------------------------------------------------------------
// Flash attention, fp16 2-term mma. 128 q-rows/CTA, 8 warps.
//   S = Q*Kh^T + Q*Kl^T ;  O = P*Vh + P*Vl  (P plain fp16)
// SMEM: Q 32KB | 2 stages x (Kh 16K | Kl 16K | Vth 16K | Vtl 16K) = 160KB.
// Writes y as plain fp16 (feeds out-proj A operand).
// ---------------------------------------------------------------------------
#define ATT_SMEM 163840

__global__ __launch_bounds__(256, 1) void flash_mma(
    const __half* __restrict__ q16,
    const __half* __restrict__ kh, const __half* __restrict__ kl,
    const __half* __restrict__ vth, const __half* __restrict__ vtl,
    __half* __restrict__ y)
{
    extern __shared__ char smem[];
    const uint32_t sb = smem_u32(smem);
    const int tid = threadIdx.x, wid = tid >> 5, lane = tid & 31;
    const int bh = blockIdx.y;
    const int b = bh >> 4, h = bh & 15;
    const int q0 = (gridDim.x - 1 - blockIdx.x) * 128;   // heavy blocks first
    const int NB = q0 / 64 + 2;

    const size_t qkbase = (size_t)bh * L_ * HD_;
    const size_t vbase  = (size_t)bh * HD_ * L_;

    // Q: [half128][(128 rows)(128B)], 32KB
    #pragma unroll
    for (int it = 0; it < 8; it++) {
        int idx = tid + 256 * it;
        int c = idx & 15, r = idx >> 4;
        const __half* src = q16 + qkbase + (size_t)(q0 + r) * 128 + c * 8;
        CP16(sb + (c >> 3) * 16384 + SWZ((uint32_t)(r * 128 + (c & 7) * 16)), src);
    }
    auto load_kv = [&](int kb, int s) {
        const uint32_t st0 = sb + 32768 + s * 65536;
        const int k0 = kb * 64;
        #pragma unroll
        for (int it = 0; it < 8; it++) {   // K hi/lo: [sp][half128][64 rows][128B]
            int idx = tid + 256 * it;
            int c = idx & 15, r = (idx >> 4) & 63, sp = idx >> 10;
            const __half* src = (sp ? kl : kh) + qkbase + (size_t)(k0 + r) * 128 + c * 8;
            CP16(st0 + sp * 16384 + (c >> 3) * 8192 + SWZ((uint32_t)(r * 128 + (c & 7) * 16)), src);
        }
        #pragma unroll
        for (int it = 0; it < 8; it++) {   // Vt hi/lo: [sp][128 hd][128B]
            int idx = tid + 256 * it;
            int c = idx & 7, r = (idx >> 3) & 127, sp = idx >> 10;
            const __half* src = (sp ? vtl : vth) + vbase + (size_t)r * L_ + k0 + c * 8;
            CP16(st0 + 32768 + sp * 16384 + SWZ((uint32_t)(r * 128 + c * 16)), src);
        }
        CP_COMMIT();
    };

    load_kv(0, 0);
    load_kv(1, 1);

    float o[16][4];
    #pragma unroll
    for (int n = 0; n < 16; n++)
        #pragma unroll
        for (int v = 0; v < 4; v++) o[n][v] = 0.f;
    float m0 = -1e30f, m1 = -1e30f, l0 = 0.f, l1 = 0.f;

    const int a_row = wid * 16 + (lane & 15);
    const uint32_t a_kb = (lane >> 4) << 4;
    const int b_row = (lane & 7) + ((lane >> 4) << 3);
    const uint32_t b_kb = ((lane >> 3) & 1) << 4;
    const float scale = 0.08838834764831845f;
    const int row0 = q0 + wid * 16 + (lane >> 2);
    const int ec = (lane & 3) * 2;

    for (int kb = 0; kb < NB; kb++) {
        const int s = kb & 1;
        if (kb == NB - 1) CP_WAIT0(); else CP_WAIT1();
        __syncthreads();
        const uint32_t st0 = sb + 32768 + s * 65536;
        const int k0 = kb * 64;

        // ---- S = Q K^T (fp16 2-term) ----
        float sc[8][4];
        #pragma unroll
        for (int n = 0; n < 8; n++)
            #pragma unroll
            for (int v = 0; v < 4; v++) sc[n][v] = 0.f;

        #pragma unroll
        for (int half = 0; half < 2; half++)
            #pragma unroll
            for (int ks = 0; ks < 4; ks++) {
                uint32_t qo = sb + half * 16384 + SWZ((uint32_t)(a_row * 128 + ks * 32 + a_kb));
                uint32_t aQ[4];
                LDSM4(aQ[0], aQ[1], aQ[2], aQ[3], qo);
                #pragma unroll
                for (int p = 0; p < 4; p++) {
                    uint32_t ko = st0 + half * 8192 + SWZ((uint32_t)((b_row + p * 16) * 128 + ks * 32 + b_kb));
                    uint32_t bH[4], bL[4];
                    LDSM4(bH[0], bH[1], bH[2], bH[3], ko);
                    LDSM4(bL[0], bL[1], bL[2], bL[3], ko + 16384);
                    mma_f16(sc[2*p],   aQ, bH[0], bH[1]);
                    mma_f16(sc[2*p],   aQ, bL[0], bL[1]);
                    mma_f16(sc[2*p+1], aQ, bH[2], bH[3]);
                    mma_f16(sc[2*p+1], aQ, bL[2], bL[3]);
                }
            }

        const bool need_mask = (kb >= NB - 2);
        #pragma unroll
        for (int n = 0; n < 8; n++)
            #pragma unroll
            for (int v = 0; v < 4; v++) {
                float val = sc[n][v] * scale;
                if (need_mask) {
                    int col = k0 + n * 8 + ec + (v & 1);
                    int row = row0 + ((v >= 2) ? 8 : 0);
                    if (col > row) val = -1e30f;
                }
                sc[n][v] = val;
            }

        float mx0 = -1e30f, mx1 = -1e30f;
        #pragma unroll
        for (int n = 0; n < 8; n++) {
            mx0 = fmaxf(mx0, fmaxf(sc[n][0], sc[n][1]));
            mx1 = fmaxf(mx1, fmaxf(sc[n][2], sc[n][3]));
        }
        mx0 = fmaxf(mx0, __shfl_xor_sync(0xffffffffu, mx0, 1));
        mx0 = fmaxf(mx0, __shfl_xor_sync(0xffffffffu, mx0, 2));
        mx1 = fmaxf(mx1, __shfl_xor_sync(0xffffffffu, mx1, 1));
        mx1 = fmaxf(mx1, __shfl_xor_sync(0xffffffffu, mx1, 2));
        float nm0 = fmaxf(m0, mx0), nm1 = fmaxf(m1, mx1);
        float al0 = __expf(m0 - nm0), al1 = __expf(m1 - nm1);
        m0 = nm0; m1 = nm1;
        float ps0 = 0.f, ps1 = 0.f;
        #pragma unroll
        for (int n = 0; n < 8; n++) {
            float p0 = __expf(sc[n][0] - m0), p1 = __expf(sc[n][1] - m0);
            float p2 = __expf(sc[n][2] - m1), p3 = __expf(sc[n][3] - m1);
            sc[n][0] = p0; sc[n][1] = p1; sc[n][2] = p2; sc[n][3] = p3;
            ps0 += p0 + p1; ps1 += p2 + p3;
        }
        l0 = l0 * al0 + ps0;
        l1 = l1 * al1 + ps1;
        #pragma unroll
        for (int n = 0; n < 16; n++) {
            o[n][0] *= al0; o[n][1] *= al0; o[n][2] *= al1; o[n][3] *= al1;
        }

        // ---- O += P V (P plain fp16) ----
        #pragma unroll
        for (int kc = 0; kc < 4; kc++) {
            uint32_t aP[4];
            aP[0] = pack_f16(sc[2*kc][0],   sc[2*kc][1]);
            aP[1] = pack_f16(sc[2*kc][2],   sc[2*kc][3]);
            aP[2] = pack_f16(sc[2*kc+1][0], sc[2*kc+1][1]);
            aP[3] = pack_f16(sc[2*kc+1][2], sc[2*kc+1][3]);
            #pragma unroll
            for (int p = 0; p < 8; p++) {
                uint32_t vo = st0 + 32768 + SWZ((uint32_t)((b_row + p * 16) * 128 + kc * 32 + b_kb));
                uint32_t bH[4], bL[4];
                LDSM4(bH[0], bH[1], bH[2], bH[3], vo);
                LDSM4(bL[0], bL[1], bL[2], bL[3], vo + 16384);
                mma_f16(o[2*p],   aP, bH[0], bH[1]);
                mma_f16(o[2*p],   aP, bL[0], bL[1]);
                mma_f16(o[2*p+1], aP, bH[2], bH[3]);
                mma_f16(o[2*p+1], aP, bL[2], bL[3]);
            }
        }
        __syncthreads();
        if (kb + 2 < NB) load_kv(kb + 2, s);
    }

    l0 += __shfl_xor_sync(0xffffffffu, l0, 1);
    l0 += __shfl_xor_sync(0xffffffffu, l0, 2);
    l1 += __shfl_xor_sync(0xffffffffu, l1, 1);
    l1 += __shfl_xor_sync(0xffffffffu, l1, 2);
    float i0 = 1.f / l0, i1 = 1.f / l1;
    const size_t rbase = (size_t)(b * L_ + row0) * D_ + h * HD_ + ec;
    #pragma unroll
    for (int n = 0; n < 16; n++) {
        size_t o0 = rbase + n * 8;
        size_t o1 = o0 + 8 * (size_t)D_;
        *(__half2*)(y + o0) = __floats2half2_rn(o[n][0] * i0, o[n][1] * i0);
        *(__half2*)(y + o1) = __floats2half2_rn(o[n][2] * i1, o[n][3] * i1);
    }
}

// ---------------------------------------------------------------------------
extern "C" void kernel_launch(void* const* d_in, const int* in_sizes, int n_in,
                              void* d_out, int out_size)
{
    const float* x     = (const float*)d_in[0];
    const float* w_qkv = (const float*)d_in[1];
    const float* w_o   = (const float*)d_in[2];
    float* out = (float*)d_out;

    float *qkv, *ct, *st;
    __half *x16, *wqh, *wql, *woh, *wol, *y16;
    __half *q16, *kh, *kl, *vth, *vtl;
    cudaGetSymbolAddress((void**)&qkv, g_qkv);
    cudaGetSymbolAddress((void**)&ct,  g_cos); cudaGetSymbolAddress((void**)&st, g_sin);
    cudaGetSymbolAddress((void**)&x16, g_x16);
    cudaGetSymbolAddress((void**)&wqh, g_wqh); cudaGetSymbolAddress((void**)&wql, g_wql);
    cudaGetSymbolAddress((void**)&woh, g_woh); cudaGetSymbolAddress((void**)&wol, g_wol);
    cudaGetSymbolAddress((void**)&y16, g_y16);
    cudaGetSymbolAddress((void**)&q16, g_q16);
    cudaGetSymbolAddress((void**)&kh,  g_kh);  cudaGetSymbolAddress((void**)&kl, g_kl);
    cudaGetSymbolAddress((void**)&vth, g_vth); cudaGetSymbolAddress((void**)&vtl, g_vtl);

    cudaFuncSetAttribute(gemm_f16x2, cudaFuncAttributeMaxDynamicSharedMemorySize, GEMM_SMEM);
    cudaFuncSetAttribute(flash_mma,  cudaFuncAttributeMaxDynamicSharedMemorySize, ATT_SMEM);

    // conversions + rope table
    cvt_f16<<<(M_ * D_ / 4) / 256, 256>>>(x, x16, M_ * D_ / 4);
    split_f16<<<(E3_ * D_ / 4) / 256, 256>>>(w_qkv, wqh, wql, E3_ * D_ / 4);
    split_f16<<<(D_ * D_ / 4) / 256, 256>>>(w_o, woh, wol, D_ * D_ / 4);
    rope_table<<<(L_ * 64) / 256, 256>>>(ct, st);

    // 1) qkv = x @ w_qkv^T   (fp16 2-term)
    gemm_f16x2<<<dim3(M_ / BM, E3_ / BN), 256, GEMM_SMEM>>>(x16, wqh, wql, qkv, M_, E3_, D_);

    // 2) fused rope + fp16 split + relayout
    qkv_split<<<dim3(L_ / 32, B_ * H_), 256>>>(qkv, ct, st, q16, kh, kl, vth, vtl);

    // 3) causal flash attention (fp16 2-term mma) -> y fp16
    flash_mma<<<dim3(L_ / 128, B_ * H_), 256, ATT_SMEM>>>(q16, kh, kl, vth, vtl, y16);

    // 4) out = y @ w_o^T     (fp16 2-term)
    gemm_f16x2<<<dim3(M_ / BM, D_ / BN), 256, GEMM_SMEM>>>(y16, woh, wol, out, M_, D_, D_);
}